// round 14
// baseline (speedup 1.0000x reference)
#include <cuda_runtime.h>
#include <cstdint>

#define B_   2
#define S_   2048
#define D_   1024
#define H_   16
#define HD_  64
#define BH_  (B_*H_)      // 32
#define M_   (B_*S_)      // 4096

// ------------------- scratch (device globals; no allocation) -------------------
__device__ float g_Q  [BH_*S_*HD_];
__device__ float g_Qd [BH_*S_*HD_];
__device__ float g_K  [BH_*S_*HD_];
__device__ float g_Kd [BH_*S_*HD_];
__device__ float g_V  [BH_*S_*HD_];
__device__ float g_defw[BH_*S_];
__device__ float g_att[M_*D_];

// ===================== helpers =====================
__device__ __forceinline__ uint32_t smem_u32(const void* p) {
    uint32_t a;
    asm("{ .reg .u64 t; cvta.to.shared.u64 t, %1; cvt.u32.u64 %0, t; }" : "=r"(a) : "l"(p));
    return a;
}
__device__ __forceinline__ void cpa16(uint32_t dst, const void* src) {
    asm volatile("cp.async.ca.shared.global [%0], [%1], 16;" :: "r"(dst), "l"(src));
}
#define CP_COMMIT() asm volatile("cp.async.commit_group;" ::: "memory")
#define CP_WAIT0()  asm volatile("cp.async.wait_group 0;" ::: "memory")

__device__ __forceinline__ float tf32_rna(float x) {
    uint32_t o; asm("cvt.rna.tf32.f32 %0, %1;" : "=r"(o) : "f"(x));
    return __uint_as_float(o);
}
__device__ __forceinline__ uint32_t tf32_u(float x) {
    uint32_t o; asm("cvt.rna.tf32.f32 %0, %1;" : "=r"(o) : "f"(x));
    return o;
}
__device__ __forceinline__ uint32_t lo_u(float x, uint32_t hi) {
    return __float_as_uint(x - __uint_as_float(hi));
}
__device__ __forceinline__ float tanh_ap(float x) {
    float y; asm("tanh.approx.f32 %0, %1;" : "=f"(y) : "f"(x)); return y;
}
// m16n8k8 tf32 MMA (sm_80+, base sm_103 OK).
// NOT volatile: pure register op -> scheduler may interleave independent MMAs.
__device__ __forceinline__ void mma8(float* c, const uint32_t* a, const uint32_t* b) {
    asm("mma.sync.aligned.m16n8k8.row.col.f32.tf32.tf32.f32 "
        "{%0,%1,%2,%3}, {%4,%5,%6,%7}, {%8,%9}, {%0,%1,%2,%3};"
        : "+f"(c[0]), "+f"(c[1]), "+f"(c[2]), "+f"(c[3])
        : "r"(a[0]), "r"(a[1]), "r"(a[2]), "r"(a[3]), "r"(b[0]), "r"(b[1]));
}

// =====================================================================
// Tensor-core TF32 GEMM, multi-problem via blockIdx.z.
// C = A @ W^T.  A pre-split into Ahi/Alo smem at staging; B cp.async raw
// + convert-on-read.  SPLIT=3: ah*bh+ah*bl+al*bh.  SPLIT=2: ah*bh+al*bh.
// Inner loop TERM-OUTER: each pass issues 16 independent MMAs
// (same-accumulator distance 16, no volatile pinning).
// MODE 0: scatter to head layout; MODE 1: linear.
// =====================================================================
template<int MODE, int SPLIT>
__global__ __launch_bounds__(256, 2)
void mma_gemm(const float* __restrict__ A0, const float* __restrict__ W0, float* __restrict__ C0,
              const float* __restrict__ A1, const float* __restrict__ W1, float* __restrict__ C1,
              const float* __restrict__ A2, const float* __restrict__ W2, float* __restrict__ C2)
{
    __shared__ float Ah[2][128][20];
    __shared__ float Al[2][128][20];
    __shared__ float Bs[2][128][20];

    const float* A = (blockIdx.z == 0) ? A0 : (blockIdx.z == 1) ? A1 : A2;
    const float* W = (blockIdx.z == 0) ? W0 : (blockIdx.z == 1) ? W1 : W2;
    float*       C = (blockIdx.z == 0) ? C0 : (blockIdx.z == 1) ? C1 : C2;

    const int tid  = threadIdx.x;
    const int lane = tid & 31;
    const int warp = tid >> 5;
    const int wm   = warp & 1;
    const int wn   = warp >> 1;
    const int fr   = lane >> 2;
    const int fc   = lane & 3;
    const int m0   = blockIdx.y << 7;
    const int n0   = blockIdx.x << 7;

    const int lr = tid >> 2;          // 0..63
    const int lc = (tid & 3) << 2;    // 0,4,8,12

    const float* Ag = A + (size_t)(m0 + lr) * D_ + lc;
    const float* Wg = W + (size_t)(n0 + lr) * D_ + lc;

    const uint32_t bAddr = smem_u32(&Bs[0][lr][lc]);
    constexpr uint32_t BUFB = 128 * 20 * 4;   // bytes per buffer
    constexpr uint32_t R64B = 64 * 20 * 4;    // +64 rows

    float acc[4][4][4];
#pragma unroll
    for (int mt = 0; mt < 4; mt++)
#pragma unroll
        for (int nt = 0; nt < 4; nt++)
#pragma unroll
            for (int q = 0; q < 4; q++) acc[mt][nt][q] = 0.f;

    // ---- prologue: slab 0 ----
    float4 a0 = *(const float4*)(Ag);
    float4 a1 = *(const float4*)(Ag + (size_t)64 * D_);
    cpa16(bAddr,        Wg);
    cpa16(bAddr + R64B, Wg + (size_t)64 * D_);
    CP_COMMIT();
    {
        float4 h0 = make_float4(tf32_rna(a0.x), tf32_rna(a0.y), tf32_rna(a0.z), tf32_rna(a0.w));
        float4 h1 = make_float4(tf32_rna(a1.x), tf32_rna(a1.y), tf32_rna(a1.z), tf32_rna(a1.w));
        *(float4*)&Ah[0][lr     ][lc] = h0;
        *(float4*)&Ah[0][lr + 64][lc] = h1;
        *(float4*)&Al[0][lr     ][lc] = make_float4(a0.x - h0.x, a0.y - h0.y, a0.z - h0.z, a0.w - h0.w);
        *(float4*)&Al[0][lr + 64][lc] = make_float4(a1.x - h1.x, a1.y - h1.y, a1.z - h1.z, a1.w - h1.w);
    }
    CP_WAIT0();
    __syncthreads();

    for (int it = 0; it < 64; ++it) {
        const int cur = it & 1;
        if (it < 63) {
            const int k0 = (it + 1) << 4;
            a0 = *(const float4*)(Ag + k0);
            a1 = *(const float4*)(Ag + (size_t)64 * D_ + k0);
            const uint32_t off = (uint32_t)(cur ^ 1) * BUFB;
            cpa16(bAddr + off,        Wg + k0);
            cpa16(bAddr + off + R64B, Wg + (size_t)64 * D_ + k0);
            CP_COMMIT();
        }
        const float (*Abh)[20] = Ah[cur];
        const float (*Abl)[20] = Al[cur];
        const float (*Bb)[20]  = Bs[cur];
#pragma unroll
        for (int ks = 0; ks < 16; ks += 8) {
            uint32_t ahi[4][4], alo[4][4], bhi[4][2], blo[4][2];
#pragma unroll
            for (int mt = 0; mt < 4; mt++) {
                const int mrow = wm * 64 + mt * 16 + fr;
                ahi[mt][0] = __float_as_uint(Abh[mrow    ][ks + fc]);
                ahi[mt][1] = __float_as_uint(Abh[mrow + 8][ks + fc]);
                ahi[mt][2] = __float_as_uint(Abh[mrow    ][ks + fc + 4]);
                ahi[mt][3] = __float_as_uint(Abh[mrow + 8][ks + fc + 4]);
                alo[mt][0] = __float_as_uint(Abl[mrow    ][ks + fc]);
                alo[mt][1] = __float_as_uint(Abl[mrow + 8][ks + fc]);
                alo[mt][2] = __float_as_uint(Abl[mrow    ][ks + fc + 4]);
                alo[mt][3] = __float_as_uint(Abl[mrow + 8][ks + fc + 4]);
            }
#pragma unroll
            for (int nt = 0; nt < 4; nt++) {
                const int nrow = wn * 32 + nt * 8 + fr;
                float b0 = Bb[nrow][ks + fc];
                float b1 = Bb[nrow][ks + fc + 4];
                bhi[nt][0] = tf32_u(b0);
                bhi[nt][1] = tf32_u(b1);
                if (SPLIT == 3) {
                    blo[nt][0] = lo_u(b0, bhi[nt][0]);
                    blo[nt][1] = lo_u(b1, bhi[nt][1]);
                }
            }
            // ---- pass 1: hi * bhi (16 independent MMAs) ----
#pragma unroll
            for (int mt = 0; mt < 4; mt++)
#pragma unroll
                for (int nt = 0; nt < 4; nt++)
                    mma8(acc[mt][nt], ahi[mt], bhi[nt]);
            // ---- pass 2: lo * bhi ----
#pragma unroll
            for (int mt = 0; mt < 4; mt++)
#pragma unroll
                for (int nt = 0; nt < 4; nt++)
                    mma8(acc[mt][nt], alo[mt], bhi[nt]);
            // ---- pass 3 (SPLIT3): hi * blo ----
            if (SPLIT == 3) {
#pragma unroll
                for (int mt = 0; mt < 4; mt++)
#pragma unroll
                    for (int nt = 0; nt < 4; nt++)
                        mma8(acc[mt][nt], ahi[mt], blo[nt]);
            }
        }
        if (it < 63) {
            const int nxt = cur ^ 1;
            float4 h0 = make_float4(tf32_rna(a0.x), tf32_rna(a0.y), tf32_rna(a0.z), tf32_rna(a0.w));
            float4 h1 = make_float4(tf32_rna(a1.x), tf32_rna(a1.y), tf32_rna(a1.z), tf32_rna(a1.w));
            *(float4*)&Ah[nxt][lr     ][lc] = h0;
            *(float4*)&Ah[nxt][lr + 64][lc] = h1;
            *(float4*)&Al[nxt][lr     ][lc] = make_float4(a0.x - h0.x, a0.y - h0.y, a0.z - h0.z, a0.w - h0.w);
            *(float4*)&Al[nxt][lr + 64][lc] = make_float4(a1.x - h1.x, a1.y - h1.y, a1.z - h1.z, a1.w - h1.w);
            CP_WAIT0();
        }
        __syncthreads();
    }

    // ---- epilogue (layout verified since R4) ----
    const int c2 = (lane & 3) << 1;
#pragma unroll
    for (int mt = 0; mt < 4; mt++) {
        const int mrow = m0 + wm * 64 + mt * 16 + fr;
#pragma unroll
        for (int nt = 0; nt < 4; nt++) {
            const int col = wn * 32 + nt * 8 + c2;
            float *d0, *d1;
            if (MODE == 0) {
                const int b  = mrow >> 11;
                const int s  = mrow & (S_ - 1);
                const int h  = (blockIdx.x << 1) + (wn >> 1);
                const int hd = ((wn & 1) << 5) + nt * 8 + c2;
                d0 = C + (size_t)((b * H_ + h) * S_ + s) * HD_ + hd;
                d1 = C + (size_t)((b * H_ + h) * S_ + (s + 8)) * HD_ + hd;
            } else {
                d0 = C + (size_t)mrow * D_ + n0 + col;
                d1 = C + (size_t)(mrow + 8) * D_ + n0 + col;
            }
            *(float2*)d0 = make_float2(acc[mt][nt][0], acc[mt][nt][1]);
            *(float2*)d1 = make_float2(acc[mt][nt][2], acc[mt][nt][3]);
        }
    }
}

// =====================================================================
// Tensor defw (R11/R12 version): def_w[bh,t] = sum_u sigmoid(0.125*qd.kd)
// 2-term QK, K tile pre-converted to tf32; sigmoid via tanh.approx.
// =====================================================================
__global__ __launch_bounds__(128)
void defw_kernel()
{
    __shared__ float Qs[64 * 68];
    __shared__ float Ks[64 * 68];     // tf32-rounded values

    const int tid  = threadIdx.x;
    const int lane = tid & 31;
    const int warp = tid >> 5;
    const int fr   = lane >> 2;
    const int fc   = lane & 3;
    const int bh   = blockIdx.y;
    const int t0   = blockIdx.x << 6;
    const int wr   = warp << 4;

    {
        const float* Qg = g_Qd + ((size_t)bh * S_ + t0) * HD_;
#pragma unroll
        for (int i = 0; i < 8; i++) {
            int e = i * 128 + tid;
            int row = e >> 4, c4 = (e & 15) << 2;
            *(float4*)&Qs[row * 68 + c4] = *(const float4*)(Qg + (size_t)row * HD_ + c4);
        }
    }

    float s0 = 0.f, s1 = 0.f;    // tanh accumulators

    for (int u0 = 0; u0 < S_; u0 += 64) {
        __syncthreads();
        {
            const float* Kg = g_Kd + ((size_t)bh * S_ + u0) * HD_;
#pragma unroll
            for (int i = 0; i < 8; i++) {
                int e = i * 128 + tid;
                int row = e >> 4, c4 = (e & 15) << 2;
                float4 v = *(const float4*)(Kg + (size_t)row * HD_ + c4);
                *(float4*)&Ks[row * 68 + c4] = make_float4(
                    tf32_rna(v.x), tf32_rna(v.y), tf32_rna(v.z), tf32_rna(v.w));
            }
        }
        __syncthreads();

        float qk[8][4];
#pragma unroll
        for (int nf = 0; nf < 8; nf++)
#pragma unroll
            for (int q = 0; q < 4; q++) qk[nf][q] = 0.f;

#pragma unroll
        for (int ks = 0; ks < 64; ks += 8) {
            const int ai = (wr + fr) * 68 + ks + fc;
            float r0 = Qs[ai], r1 = Qs[ai + 8 * 68], r2 = Qs[ai + 4], r3 = Qs[ai + 8 * 68 + 4];
            uint32_t ah[4] = {tf32_u(r0), tf32_u(r1), tf32_u(r2), tf32_u(r3)};
            uint32_t al[4] = {lo_u(r0, ah[0]), lo_u(r1, ah[1]), lo_u(r2, ah[2]), lo_u(r3, ah[3])};
#pragma unroll
            for (int nf = 0; nf < 8; nf++) {
                const int bi = (nf * 8 + fr) * 68 + ks + fc;
                uint32_t bh2[2] = {__float_as_uint(Ks[bi]), __float_as_uint(Ks[bi + 4])};
                mma8(qk[nf], ah, bh2);
                mma8(qk[nf], al, bh2);
            }
        }
        // sigmoid(x) = 0.5 + 0.5*tanh(x/2), x = 0.125*qk -> tanh(0.0625*qk)
#pragma unroll
        for (int nf = 0; nf < 8; nf++) {
            s0 += tanh_ap(0.0625f * qk[nf][0]);
            s0 += tanh_ap(0.0625f * qk[nf][1]);
            s1 += tanh_ap(0.0625f * qk[nf][2]);
            s1 += tanh_ap(0.0625f * qk[nf][3]);
        }
    }

    s0 += __shfl_xor_sync(0xffffffffu, s0, 1);
    s0 += __shfl_xor_sync(0xffffffffu, s0, 2);
    s1 += __shfl_xor_sync(0xffffffffu, s1, 1);
    s1 += __shfl_xor_sync(0xffffffffu, s1, 2);
    if (fc == 0) {
        g_defw[bh * S_ + t0 + wr + fr    ] = 1024.f + 0.5f * s0;
        g_defw[bh * S_ + t0 + wr + fr + 8] = 1024.f + 0.5f * s1;
    }
}

// =====================================================================
// Tensor flash attention (R9/R12 structure; mma8 now non-volatile so the
// scheduler can interleave the split-term MMAs across nf):
// logits = 0.125*(q.k)*defw[t], online softmax, O = P@V.
// CTA = 64 queries, 4 warps x 16 rows.  QK: 3xTF32.
// PV: 2-term (P.Vhi + P.Vlo), V single tile, convert-on-read.
// =====================================================================
__global__ __launch_bounds__(128)
void flash_kernel()
{
    extern __shared__ float sm[];
    float* Qs  = sm;                // [64][68]
    float* Ks  = sm + 64 * 68;
    float* Vs  = sm + 2 * 64 * 68;
    float* Ps  = sm + 3 * 64 * 68;
    float* dws = sm + 4 * 64 * 68;  // [64]

    const int tid  = threadIdx.x;
    const int lane = tid & 31;
    const int warp = tid >> 5;
    const int fr   = lane >> 2;
    const int fc   = lane & 3;
    const int bh   = blockIdx.y;
    const int s0   = blockIdx.x << 6;
    const int wr   = warp << 4;

    {
        const float* Qg = g_Q + ((size_t)bh * S_ + s0) * HD_;
#pragma unroll
        for (int i = 0; i < 8; i++) {
            int e = i * 128 + tid;
            int row = e >> 4, c4 = (e & 15) << 2;
            *(float4*)&Qs[row * 68 + c4] = *(const float4*)(Qg + (size_t)row * HD_ + c4);
        }
    }

    float o[8][4];
#pragma unroll
    for (int nf = 0; nf < 8; nf++)
#pragma unroll
        for (int q = 0; q < 4; q++) o[nf][q] = 0.f;
    float mr0 = -1e30f, mr1 = -1e30f, ls0 = 0.f, ls1 = 0.f;

    for (int t0 = 0; t0 < S_; t0 += 64) {
        __syncthreads();
        {
            const float* Kg = g_K + ((size_t)bh * S_ + t0) * HD_;
            const float* Vg = g_V + ((size_t)bh * S_ + t0) * HD_;
#pragma unroll
            for (int i = 0; i < 8; i++) {
                int e = i * 128 + tid;
                int row = e >> 4, c4 = (e & 15) << 2;
                *(float4*)&Ks[row * 68 + c4] = *(const float4*)(Kg + (size_t)row * HD_ + c4);
                *(float4*)&Vs[row * 68 + c4] = *(const float4*)(Vg + (size_t)row * HD_ + c4);
            }
            if (tid < 64) dws[tid] = 0.125f * g_defw[bh * S_ + t0 + tid];
        }
        __syncthreads();

        // ---- QK (3xTF32) ----
        float qk[8][4];
#pragma unroll
        for (int nf = 0; nf < 8; nf++)
#pragma unroll
            for (int q = 0; q < 4; q++) qk[nf][q] = 0.f;

#pragma unroll
        for (int ks = 0; ks < 64; ks += 8) {
            const int ai = (wr + fr) * 68 + ks + fc;
            float r0 = Qs[ai], r1 = Qs[ai + 8 * 68], r2 = Qs[ai + 4], r3 = Qs[ai + 8 * 68 + 4];
            uint32_t ah[4] = {tf32_u(r0), tf32_u(r1), tf32_u(r2), tf32_u(r3)};
            uint32_t al[4] = {lo_u(r0, ah[0]), lo_u(r1, ah[1]), lo_u(r2, ah[2]), lo_u(r3, ah[3])};
#pragma unroll
            for (int nf = 0; nf < 8; nf++) {
                const int bi = (nf * 8 + fr) * 68 + ks + fc;
                float b0 = Ks[bi], b1 = Ks[bi + 4];
                uint32_t bh2[2] = {tf32_u(b0), tf32_u(b1)};
                uint32_t bl2[2] = {lo_u(b0, bh2[0]), lo_u(b1, bh2[1])};
                mma8(qk[nf], ah, bh2);
                mma8(qk[nf], ah, bl2);
                mma8(qk[nf], al, bh2);
            }
        }

        // ---- logits + online softmax ----
        float nm0 = mr0, nm1 = mr1;
#pragma unroll
        for (int nf = 0; nf < 8; nf++) {
            float dw0 = dws[nf * 8 + 2 * fc];
            float dw1 = dws[nf * 8 + 2 * fc + 1];
            qk[nf][0] *= dw0; qk[nf][1] *= dw1;
            qk[nf][2] *= dw0; qk[nf][3] *= dw1;
            nm0 = fmaxf(nm0, fmaxf(qk[nf][0], qk[nf][1]));
            nm1 = fmaxf(nm1, fmaxf(qk[nf][2], qk[nf][3]));
        }
        nm0 = fmaxf(nm0, __shfl_xor_sync(0xffffffffu, nm0, 1));
        nm0 = fmaxf(nm0, __shfl_xor_sync(0xffffffffu, nm0, 2));
        nm1 = fmaxf(nm1, __shfl_xor_sync(0xffffffffu, nm1, 1));
        nm1 = fmaxf(nm1, __shfl_xor_sync(0xffffffffu, nm1, 2));
        const float al0 = __expf(mr0 - nm0);
        const float al1 = __expf(mr1 - nm1);
        mr0 = nm0; mr1 = nm1;

        float rs0 = 0.f, rs1 = 0.f;
#pragma unroll
        for (int nf = 0; nf < 8; nf++) {
            float p0 = tf32_rna(__expf(qk[nf][0] - nm0));
            float p1 = tf32_rna(__expf(qk[nf][1] - nm0));
            float p2 = tf32_rna(__expf(qk[nf][2] - nm1));
            float p3 = tf32_rna(__expf(qk[nf][3] - nm1));
            rs0 += p0 + p1; rs1 += p2 + p3;
            *(float2*)&Ps[(wr + fr    ) * 68 + nf * 8 + 2 * fc] = make_float2(p0, p1);
            *(float2*)&Ps[(wr + fr + 8) * 68 + nf * 8 + 2 * fc] = make_float2(p2, p3);
        }
        rs0 += __shfl_xor_sync(0xffffffffu, rs0, 1);
        rs0 += __shfl_xor_sync(0xffffffffu, rs0, 2);
        rs1 += __shfl_xor_sync(0xffffffffu, rs1, 1);
        rs1 += __shfl_xor_sync(0xffffffffu, rs1, 2);
        ls0 = ls0 * al0 + rs0;
        ls1 = ls1 * al1 + rs1;
#pragma unroll
        for (int nf = 0; nf < 8; nf++) {
            o[nf][0] *= al0; o[nf][1] *= al0;
            o[nf][2] *= al1; o[nf][3] *= al1;
        }
        __syncwarp();

        // ---- PV: O += P @ V  (V split hi/lo, convert-on-read) ----
#pragma unroll
        for (int ks = 0; ks < 64; ks += 8) {
            const int ai = (wr + fr) * 68 + ks + fc;
            uint32_t pa[4] = {
                __float_as_uint(Ps[ai]),
                __float_as_uint(Ps[ai + 8 * 68]),
                __float_as_uint(Ps[ai + 4]),
                __float_as_uint(Ps[ai + 8 * 68 + 4])};
#pragma unroll
            for (int nf = 0; nf < 8; nf++) {
                const int bi = (ks + fc) * 68 + nf * 8 + fr;
                float b0 = Vs[bi], b1 = Vs[bi + 4 * 68];
                uint32_t vh[2] = {tf32_u(b0), tf32_u(b1)};
                uint32_t vl[2] = {lo_u(b0, vh[0]), lo_u(b1, vh[1])};
                mma8(o[nf], pa, vh);
                mma8(o[nf], pa, vl);
            }
        }
    }

    const float inv0 = __fdividef(1.f, ls0);
    const float inv1 = __fdividef(1.f, ls1);
    const int b = bh >> 4, h = bh & 15;
    float* base0 = g_att + (size_t)(b * S_ + s0 + wr + fr) * D_ + h * HD_;
    float* base1 = base0 + (size_t)8 * D_;
#pragma unroll
    for (int nf = 0; nf < 8; nf++) {
        *(float2*)(base0 + nf * 8 + 2 * fc) = make_float2(o[nf][0] * inv0, o[nf][1] * inv0);
        *(float2*)(base1 + nf * 8 + 2 * fc) = make_float2(o[nf][2] * inv1, o[nf][3] * inv1);
    }
}

// =====================================================================
extern "C" void kernel_launch(void* const* d_in, const int* in_sizes, int n_in,
                              void* d_out, int out_size)
{
    const float* qi  = (const float*)d_in[0];
    const float* ki  = (const float*)d_in[1];
    const float* vi  = (const float*)d_in[2];
    const float* Wq  = (const float*)d_in[3];
    const float* Wqd = (const float*)d_in[4];
    const float* Wk  = (const float*)d_in[5];
    const float* Wkd = (const float*)d_in[6];
    const float* Wv  = (const float*)d_in[7];
    const float* Wo  = (const float*)d_in[8];
    float* out = (float*)d_out;

    float *pQ, *pQd, *pK, *pKd, *pV, *pAtt;
    cudaGetSymbolAddress((void**)&pQ,  g_Q);
    cudaGetSymbolAddress((void**)&pQd, g_Qd);
    cudaGetSymbolAddress((void**)&pK,  g_K);
    cudaGetSymbolAddress((void**)&pKd, g_Kd);
    cudaGetSymbolAddress((void**)&pV,  g_V);
    cudaGetSymbolAddress((void**)&pAtt, g_att);

    const int FLASH_SMEM = (4 * 64 * 68 + 64) * 4;   // 69888 B
    static int configured = 0;
    if (!configured) {
        cudaFuncSetAttribute(flash_kernel, cudaFuncAttributeMaxDynamicSharedMemorySize, FLASH_SMEM);
        configured = 1;
    }

    dim3 blk(256);

    // score-path projections (3-term): Wq, Wk   -- fused, z in {0,1}
    mma_gemm<0,3><<<dim3(8, 32, 2), blk>>>(qi, Wq, pQ,
                                           ki, Wk, pK,
                                           qi, Wq, pQ);
    // tolerant projections (2-term): Wqd, Wkd, Wv -- fused, z in {0,1,2}
    mma_gemm<0,2><<<dim3(8, 32, 3), blk>>>(qi, Wqd, pQd,
                                           ki, Wkd, pKd,
                                           vi, Wv,  pV);

    defw_kernel <<<dim3(32, 32), dim3(128)>>>();
    flash_kernel<<<dim3(32, 32), dim3(128), FLASH_SMEM>>>();

    // output projection (2-term)
    mma_gemm<1,2><<<dim3(8, 32, 1), blk>>>(pAtt, Wo, out,
                                           pAtt, Wo, out,
                                           pAtt, Wo, out);
}

// round 15
// speedup vs baseline: 1.1143x; 1.1143x over previous
#include <cuda_runtime.h>
#include <cstdint>

#define B_   2
#define S_   2048
#define D_   1024
#define H_   16
#define HD_  64
#define BH_  (B_*H_)      // 32
#define M_   (B_*S_)      // 4096

// ------------------- scratch (device globals; no allocation) -------------------
__device__ float g_Q  [BH_*S_*HD_];
__device__ float g_Qd [BH_*S_*HD_];
__device__ float g_K  [BH_*S_*HD_];
__device__ float g_Kd [BH_*S_*HD_];
__device__ float g_V  [BH_*S_*HD_];
__device__ float g_defw[BH_*S_];
__device__ float g_att[M_*D_];

// ===================== helpers =====================
__device__ __forceinline__ uint32_t smem_u32(const void* p) {
    uint32_t a;
    asm("{ .reg .u64 t; cvta.to.shared.u64 t, %1; cvt.u32.u64 %0, t; }" : "=r"(a) : "l"(p));
    return a;
}
__device__ __forceinline__ void cpa16(uint32_t dst, const void* src) {
    asm volatile("cp.async.ca.shared.global [%0], [%1], 16;" :: "r"(dst), "l"(src));
}
#define CP_COMMIT() asm volatile("cp.async.commit_group;" ::: "memory")
#define CP_WAIT0()  asm volatile("cp.async.wait_group 0;" ::: "memory")

__device__ __forceinline__ float tf32_rna(float x) {
    uint32_t o; asm("cvt.rna.tf32.f32 %0, %1;" : "=r"(o) : "f"(x));
    return __uint_as_float(o);
}
__device__ __forceinline__ uint32_t tf32_u(float x) {
    uint32_t o; asm("cvt.rna.tf32.f32 %0, %1;" : "=r"(o) : "f"(x));
    return o;
}
__device__ __forceinline__ uint32_t lo_u(float x, uint32_t hi) {
    return __float_as_uint(x - __uint_as_float(hi));
}
__device__ __forceinline__ float tanh_ap(float x) {
    float y; asm("tanh.approx.f32 %0, %1;" : "=f"(y) : "f"(x)); return y;
}
// m16n8k8 tf32 MMA (sm_80+, base sm_103 OK)
__device__ __forceinline__ void mma8(float* c, const uint32_t* a, const uint32_t* b) {
    asm("mma.sync.aligned.m16n8k8.row.col.f32.tf32.tf32.f32 "
        "{%0,%1,%2,%3}, {%4,%5,%6,%7}, {%8,%9}, {%0,%1,%2,%3};"
        : "+f"(c[0]), "+f"(c[1]), "+f"(c[2]), "+f"(c[3])
        : "r"(a[0]), "r"(a[1]), "r"(a[2]), "r"(a[3]), "r"(b[0]), "r"(b[1]));
}

// =====================================================================
// Tensor-core TF32 GEMM, multi-problem via blockIdx.z (best-known R13).
// C = A @ W^T.  A pre-split into Ahi/Alo smem; B cp.async + cvt-on-read.
// SPLIT=3: ah*bh+al*bh+ah*bl.  SPLIT=2: ah*bh+al*bh.
// MODE 0: scatter to head layout; MODE 1: linear.
// =====================================================================
template<int MODE, int SPLIT>
__global__ __launch_bounds__(256, 2)
void mma_gemm(const float* __restrict__ A0, const float* __restrict__ W0, float* __restrict__ C0,
              const float* __restrict__ A1, const float* __restrict__ W1, float* __restrict__ C1,
              const float* __restrict__ A2, const float* __restrict__ W2, float* __restrict__ C2)
{
    __shared__ float Ah[2][128][20];
    __shared__ float Al[2][128][20];
    __shared__ float Bs[2][128][20];

    const float* A = (blockIdx.z == 0) ? A0 : (blockIdx.z == 1) ? A1 : A2;
    const float* W = (blockIdx.z == 0) ? W0 : (blockIdx.z == 1) ? W1 : W2;
    float*       C = (blockIdx.z == 0) ? C0 : (blockIdx.z == 1) ? C1 : C2;

    const int tid  = threadIdx.x;
    const int lane = tid & 31;
    const int warp = tid >> 5;
    const int wm   = warp & 1;
    const int wn   = warp >> 1;
    const int fr   = lane >> 2;
    const int fc   = lane & 3;
    const int m0   = blockIdx.y << 7;
    const int n0   = blockIdx.x << 7;

    const int lr = tid >> 2;          // 0..63
    const int lc = (tid & 3) << 2;    // 0,4,8,12

    const float* Ag = A + (size_t)(m0 + lr) * D_ + lc;
    const float* Wg = W + (size_t)(n0 + lr) * D_ + lc;

    const uint32_t bAddr = smem_u32(&Bs[0][lr][lc]);
    constexpr uint32_t BUFB = 128 * 20 * 4;   // bytes per buffer
    constexpr uint32_t R64B = 64 * 20 * 4;    // +64 rows

    float acc[4][4][4];
#pragma unroll
    for (int mt = 0; mt < 4; mt++)
#pragma unroll
        for (int nt = 0; nt < 4; nt++)
#pragma unroll
            for (int q = 0; q < 4; q++) acc[mt][nt][q] = 0.f;

    // ---- prologue: slab 0 ----
    float4 a0 = *(const float4*)(Ag);
    float4 a1 = *(const float4*)(Ag + (size_t)64 * D_);
    cpa16(bAddr,        Wg);
    cpa16(bAddr + R64B, Wg + (size_t)64 * D_);
    CP_COMMIT();
    {
        float4 h0 = make_float4(tf32_rna(a0.x), tf32_rna(a0.y), tf32_rna(a0.z), tf32_rna(a0.w));
        float4 h1 = make_float4(tf32_rna(a1.x), tf32_rna(a1.y), tf32_rna(a1.z), tf32_rna(a1.w));
        *(float4*)&Ah[0][lr     ][lc] = h0;
        *(float4*)&Ah[0][lr + 64][lc] = h1;
        *(float4*)&Al[0][lr     ][lc] = make_float4(a0.x - h0.x, a0.y - h0.y, a0.z - h0.z, a0.w - h0.w);
        *(float4*)&Al[0][lr + 64][lc] = make_float4(a1.x - h1.x, a1.y - h1.y, a1.z - h1.z, a1.w - h1.w);
    }
    CP_WAIT0();
    __syncthreads();

    for (int it = 0; it < 64; ++it) {
        const int cur = it & 1;
        if (it < 63) {
            const int k0 = (it + 1) << 4;
            a0 = *(const float4*)(Ag + k0);
            a1 = *(const float4*)(Ag + (size_t)64 * D_ + k0);
            const uint32_t off = (uint32_t)(cur ^ 1) * BUFB;
            cpa16(bAddr + off,        Wg + k0);
            cpa16(bAddr + off + R64B, Wg + (size_t)64 * D_ + k0);
            CP_COMMIT();
        }
        const float (*Abh)[20] = Ah[cur];
        const float (*Abl)[20] = Al[cur];
        const float (*Bb)[20]  = Bs[cur];
#pragma unroll
        for (int ks = 0; ks < 16; ks += 8) {
            uint32_t ahi[4][4], alo[4][4], bhi[4][2], blo[4][2];
#pragma unroll
            for (int mt = 0; mt < 4; mt++) {
                const int mrow = wm * 64 + mt * 16 + fr;
                ahi[mt][0] = __float_as_uint(Abh[mrow    ][ks + fc]);
                ahi[mt][1] = __float_as_uint(Abh[mrow + 8][ks + fc]);
                ahi[mt][2] = __float_as_uint(Abh[mrow    ][ks + fc + 4]);
                ahi[mt][3] = __float_as_uint(Abh[mrow + 8][ks + fc + 4]);
                alo[mt][0] = __float_as_uint(Abl[mrow    ][ks + fc]);
                alo[mt][1] = __float_as_uint(Abl[mrow + 8][ks + fc]);
                alo[mt][2] = __float_as_uint(Abl[mrow    ][ks + fc + 4]);
                alo[mt][3] = __float_as_uint(Abl[mrow + 8][ks + fc + 4]);
            }
#pragma unroll
            for (int nt = 0; nt < 4; nt++) {
                const int nrow = wn * 32 + nt * 8 + fr;
                float b0 = Bb[nrow][ks + fc];
                float b1 = Bb[nrow][ks + fc + 4];
                bhi[nt][0] = tf32_u(b0);
                bhi[nt][1] = tf32_u(b1);
                if (SPLIT == 3) {
                    blo[nt][0] = lo_u(b0, bhi[nt][0]);
                    blo[nt][1] = lo_u(b1, bhi[nt][1]);
                }
            }
#pragma unroll
            for (int mt = 0; mt < 4; mt++)
#pragma unroll
                for (int nt = 0; nt < 4; nt++)
                    mma8(acc[mt][nt], ahi[mt], bhi[nt]);
#pragma unroll
            for (int mt = 0; mt < 4; mt++)
#pragma unroll
                for (int nt = 0; nt < 4; nt++)
                    mma8(acc[mt][nt], alo[mt], bhi[nt]);
            if (SPLIT == 3) {
#pragma unroll
                for (int mt = 0; mt < 4; mt++)
#pragma unroll
                    for (int nt = 0; nt < 4; nt++)
                        mma8(acc[mt][nt], ahi[mt], blo[nt]);
            }
        }
        if (it < 63) {
            const int nxt = cur ^ 1;
            float4 h0 = make_float4(tf32_rna(a0.x), tf32_rna(a0.y), tf32_rna(a0.z), tf32_rna(a0.w));
            float4 h1 = make_float4(tf32_rna(a1.x), tf32_rna(a1.y), tf32_rna(a1.z), tf32_rna(a1.w));
            *(float4*)&Ah[nxt][lr     ][lc] = h0;
            *(float4*)&Ah[nxt][lr + 64][lc] = h1;
            *(float4*)&Al[nxt][lr     ][lc] = make_float4(a0.x - h0.x, a0.y - h0.y, a0.z - h0.z, a0.w - h0.w);
            *(float4*)&Al[nxt][lr + 64][lc] = make_float4(a1.x - h1.x, a1.y - h1.y, a1.z - h1.z, a1.w - h1.w);
            CP_WAIT0();
        }
        __syncthreads();
    }

    // ---- epilogue (layout verified since R4) ----
    const int c2 = (lane & 3) << 1;
#pragma unroll
    for (int mt = 0; mt < 4; mt++) {
        const int mrow = m0 + wm * 64 + mt * 16 + fr;
#pragma unroll
        for (int nt = 0; nt < 4; nt++) {
            const int col = wn * 32 + nt * 8 + c2;
            float *d0, *d1;
            if (MODE == 0) {
                const int b  = mrow >> 11;
                const int s  = mrow & (S_ - 1);
                const int h  = (blockIdx.x << 1) + (wn >> 1);
                const int hd = ((wn & 1) << 5) + nt * 8 + c2;
                d0 = C + (size_t)((b * H_ + h) * S_ + s) * HD_ + hd;
                d1 = C + (size_t)((b * H_ + h) * S_ + (s + 8)) * HD_ + hd;
            } else {
                d0 = C + (size_t)mrow * D_ + n0 + col;
                d1 = C + (size_t)(mrow + 8) * D_ + n0 + col;
            }
            *(float2*)d0 = make_float2(acc[mt][nt][0], acc[mt][nt][1]);
            *(float2*)d1 = make_float2(acc[mt][nt][2], acc[mt][nt][3]);
        }
    }
}

// =====================================================================
// Tensor defw: def_w[bh,t] = sum_u sigmoid(0.125 * qd[t].kd[u])
// 1-term QK (hi*hi only): defw enters logits multiplicatively at ~1024,
// so its absolute error (~2e-3) is ~2e-6 relative -> negligible.
// K tile pre-converted to tf32.  sigmoid via tanh.approx.
// =====================================================================
__global__ __launch_bounds__(128)
void defw_kernel()
{
    __shared__ float Qs[64 * 68];
    __shared__ float Ks[64 * 68];     // tf32-rounded values

    const int tid  = threadIdx.x;
    const int lane = tid & 31;
    const int warp = tid >> 5;
    const int fr   = lane >> 2;
    const int fc   = lane & 3;
    const int bh   = blockIdx.y;
    const int t0   = blockIdx.x << 6;
    const int wr   = warp << 4;

    {
        const float* Qg = g_Qd + ((size_t)bh * S_ + t0) * HD_;
#pragma unroll
        for (int i = 0; i < 8; i++) {
            int e = i * 128 + tid;
            int row = e >> 4, c4 = (e & 15) << 2;
            *(float4*)&Qs[row * 68 + c4] = *(const float4*)(Qg + (size_t)row * HD_ + c4);
        }
    }

    float s0 = 0.f, s1 = 0.f;    // tanh accumulators

    for (int u0 = 0; u0 < S_; u0 += 64) {
        __syncthreads();
        {
            const float* Kg = g_Kd + ((size_t)bh * S_ + u0) * HD_;
#pragma unroll
            for (int i = 0; i < 8; i++) {
                int e = i * 128 + tid;
                int row = e >> 4, c4 = (e & 15) << 2;
                float4 v = *(const float4*)(Kg + (size_t)row * HD_ + c4);
                *(float4*)&Ks[row * 68 + c4] = make_float4(
                    tf32_rna(v.x), tf32_rna(v.y), tf32_rna(v.z), tf32_rna(v.w));
            }
        }
        __syncthreads();

        float qk[8][4];
#pragma unroll
        for (int nf = 0; nf < 8; nf++)
#pragma unroll
            for (int q = 0; q < 4; q++) qk[nf][q] = 0.f;

#pragma unroll
        for (int ks = 0; ks < 64; ks += 8) {
            const int ai = (wr + fr) * 68 + ks + fc;
            uint32_t ah[4] = {tf32_u(Qs[ai]), tf32_u(Qs[ai + 8 * 68]),
                              tf32_u(Qs[ai + 4]), tf32_u(Qs[ai + 8 * 68 + 4])};
#pragma unroll
            for (int nf = 0; nf < 8; nf++) {
                const int bi = (nf * 8 + fr) * 68 + ks + fc;
                uint32_t bh2[2] = {__float_as_uint(Ks[bi]), __float_as_uint(Ks[bi + 4])};
                mma8(qk[nf], ah, bh2);
            }
        }
        // sigmoid(x) = 0.5 + 0.5*tanh(x/2), x = 0.125*qk -> tanh(0.0625*qk)
#pragma unroll
        for (int nf = 0; nf < 8; nf++) {
            s0 += tanh_ap(0.0625f * qk[nf][0]);
            s0 += tanh_ap(0.0625f * qk[nf][1]);
            s1 += tanh_ap(0.0625f * qk[nf][2]);
            s1 += tanh_ap(0.0625f * qk[nf][3]);
        }
    }

    s0 += __shfl_xor_sync(0xffffffffu, s0, 1);
    s0 += __shfl_xor_sync(0xffffffffu, s0, 2);
    s1 += __shfl_xor_sync(0xffffffffu, s1, 1);
    s1 += __shfl_xor_sync(0xffffffffu, s1, 2);
    if (fc == 0) {
        g_defw[bh * S_ + t0 + wr + fr    ] = 1024.f + 0.5f * s0;
        g_defw[bh * S_ + t0 + wr + fr + 8] = 1024.f + 0.5f * s1;
    }
}

// =====================================================================
// Tensor flash attention: logits = 0.125*(q.k)*defw[t], online softmax,
// O = P@V.  CTA = 64 queries, 4 warps x 16 rows.
// QK: 3xTF32 (score path -- untouchable).
// PV: 1-term (P.Vhi only) -- V rounding enters output linearly ~2e-4.
// =====================================================================
__global__ __launch_bounds__(128)
void flash_kernel()
{
    extern __shared__ float sm[];
    float* Qs  = sm;                // [64][68]
    float* Ks  = sm + 64 * 68;
    float* Vs  = sm + 2 * 64 * 68;
    float* Ps  = sm + 3 * 64 * 68;
    float* dws = sm + 4 * 64 * 68;  // [64]

    const int tid  = threadIdx.x;
    const int lane = tid & 31;
    const int warp = tid >> 5;
    const int fr   = lane >> 2;
    const int fc   = lane & 3;
    const int bh   = blockIdx.y;
    const int s0   = blockIdx.x << 6;
    const int wr   = warp << 4;

    {
        const float* Qg = g_Q + ((size_t)bh * S_ + s0) * HD_;
#pragma unroll
        for (int i = 0; i < 8; i++) {
            int e = i * 128 + tid;
            int row = e >> 4, c4 = (e & 15) << 2;
            *(float4*)&Qs[row * 68 + c4] = *(const float4*)(Qg + (size_t)row * HD_ + c4);
        }
    }

    float o[8][4];
#pragma unroll
    for (int nf = 0; nf < 8; nf++)
#pragma unroll
        for (int q = 0; q < 4; q++) o[nf][q] = 0.f;
    float mr0 = -1e30f, mr1 = -1e30f, ls0 = 0.f, ls1 = 0.f;

    for (int t0 = 0; t0 < S_; t0 += 64) {
        __syncthreads();
        {
            const float* Kg = g_K + ((size_t)bh * S_ + t0) * HD_;
            const float* Vg = g_V + ((size_t)bh * S_ + t0) * HD_;
#pragma unroll
            for (int i = 0; i < 8; i++) {
                int e = i * 128 + tid;
                int row = e >> 4, c4 = (e & 15) << 2;
                *(float4*)&Ks[row * 68 + c4] = *(const float4*)(Kg + (size_t)row * HD_ + c4);
                float4 v = *(const float4*)(Vg + (size_t)row * HD_ + c4);
                *(float4*)&Vs[row * 68 + c4] = make_float4(
                    tf32_rna(v.x), tf32_rna(v.y), tf32_rna(v.z), tf32_rna(v.w));
            }
            if (tid < 64) dws[tid] = 0.125f * g_defw[bh * S_ + t0 + tid];
        }
        __syncthreads();

        // ---- QK (3xTF32) ----
        float qk[8][4];
#pragma unroll
        for (int nf = 0; nf < 8; nf++)
#pragma unroll
            for (int q = 0; q < 4; q++) qk[nf][q] = 0.f;

#pragma unroll
        for (int ks = 0; ks < 64; ks += 8) {
            const int ai = (wr + fr) * 68 + ks + fc;
            float r0 = Qs[ai], r1 = Qs[ai + 8 * 68], r2 = Qs[ai + 4], r3 = Qs[ai + 8 * 68 + 4];
            uint32_t ah[4] = {tf32_u(r0), tf32_u(r1), tf32_u(r2), tf32_u(r3)};
            uint32_t al[4] = {lo_u(r0, ah[0]), lo_u(r1, ah[1]), lo_u(r2, ah[2]), lo_u(r3, ah[3])};
#pragma unroll
            for (int nf = 0; nf < 8; nf++) {
                const int bi = (nf * 8 + fr) * 68 + ks + fc;
                float b0 = Ks[bi], b1 = Ks[bi + 4];
                uint32_t bh2[2] = {tf32_u(b0), tf32_u(b1)};
                uint32_t bl2[2] = {lo_u(b0, bh2[0]), lo_u(b1, bh2[1])};
                mma8(qk[nf], ah, bh2);
                mma8(qk[nf], ah, bl2);
                mma8(qk[nf], al, bh2);
            }
        }

        // ---- logits + online softmax ----
        float nm0 = mr0, nm1 = mr1;
#pragma unroll
        for (int nf = 0; nf < 8; nf++) {
            float dw0 = dws[nf * 8 + 2 * fc];
            float dw1 = dws[nf * 8 + 2 * fc + 1];
            qk[nf][0] *= dw0; qk[nf][1] *= dw1;
            qk[nf][2] *= dw0; qk[nf][3] *= dw1;
            nm0 = fmaxf(nm0, fmaxf(qk[nf][0], qk[nf][1]));
            nm1 = fmaxf(nm1, fmaxf(qk[nf][2], qk[nf][3]));
        }
        nm0 = fmaxf(nm0, __shfl_xor_sync(0xffffffffu, nm0, 1));
        nm0 = fmaxf(nm0, __shfl_xor_sync(0xffffffffu, nm0, 2));
        nm1 = fmaxf(nm1, __shfl_xor_sync(0xffffffffu, nm1, 1));
        nm1 = fmaxf(nm1, __shfl_xor_sync(0xffffffffu, nm1, 2));
        const float al0 = __expf(mr0 - nm0);
        const float al1 = __expf(mr1 - nm1);
        mr0 = nm0; mr1 = nm1;

        float rs0 = 0.f, rs1 = 0.f;
#pragma unroll
        for (int nf = 0; nf < 8; nf++) {
            float p0 = tf32_rna(__expf(qk[nf][0] - nm0));
            float p1 = tf32_rna(__expf(qk[nf][1] - nm0));
            float p2 = tf32_rna(__expf(qk[nf][2] - nm1));
            float p3 = tf32_rna(__expf(qk[nf][3] - nm1));
            rs0 += p0 + p1; rs1 += p2 + p3;
            *(float2*)&Ps[(wr + fr    ) * 68 + nf * 8 + 2 * fc] = make_float2(p0, p1);
            *(float2*)&Ps[(wr + fr + 8) * 68 + nf * 8 + 2 * fc] = make_float2(p2, p3);
        }
        rs0 += __shfl_xor_sync(0xffffffffu, rs0, 1);
        rs0 += __shfl_xor_sync(0xffffffffu, rs0, 2);
        rs1 += __shfl_xor_sync(0xffffffffu, rs1, 1);
        rs1 += __shfl_xor_sync(0xffffffffu, rs1, 2);
        ls0 = ls0 * al0 + rs0;
        ls1 = ls1 * al1 + rs1;
#pragma unroll
        for (int nf = 0; nf < 8; nf++) {
            o[nf][0] *= al0; o[nf][1] *= al0;
            o[nf][2] *= al1; o[nf][3] *= al1;
        }
        __syncwarp();

        // ---- PV: O += P @ Vhi  (1-term; V tile already tf32-rounded) ----
#pragma unroll
        for (int ks = 0; ks < 64; ks += 8) {
            const int ai = (wr + fr) * 68 + ks + fc;
            uint32_t pa[4] = {
                __float_as_uint(Ps[ai]),
                __float_as_uint(Ps[ai + 8 * 68]),
                __float_as_uint(Ps[ai + 4]),
                __float_as_uint(Ps[ai + 8 * 68 + 4])};
#pragma unroll
            for (int nf = 0; nf < 8; nf++) {
                const int bi = (ks + fc) * 68 + nf * 8 + fr;
                uint32_t vh[2] = {__float_as_uint(Vs[bi]), __float_as_uint(Vs[bi + 4 * 68])};
                mma8(o[nf], pa, vh);
            }
        }
    }

    const float inv0 = __fdividef(1.f, ls0);
    const float inv1 = __fdividef(1.f, ls1);
    const int b = bh >> 4, h = bh & 15;
    float* base0 = g_att + (size_t)(b * S_ + s0 + wr + fr) * D_ + h * HD_;
    float* base1 = base0 + (size_t)8 * D_;
#pragma unroll
    for (int nf = 0; nf < 8; nf++) {
        *(float2*)(base0 + nf * 8 + 2 * fc) = make_float2(o[nf][0] * inv0, o[nf][1] * inv0);
        *(float2*)(base1 + nf * 8 + 2 * fc) = make_float2(o[nf][2] * inv1, o[nf][3] * inv1);
    }
}

// =====================================================================
extern "C" void kernel_launch(void* const* d_in, const int* in_sizes, int n_in,
                              void* d_out, int out_size)
{
    const float* qi  = (const float*)d_in[0];
    const float* ki  = (const float*)d_in[1];
    const float* vi  = (const float*)d_in[2];
    const float* Wq  = (const float*)d_in[3];
    const float* Wqd = (const float*)d_in[4];
    const float* Wk  = (const float*)d_in[5];
    const float* Wkd = (const float*)d_in[6];
    const float* Wv  = (const float*)d_in[7];
    const float* Wo  = (const float*)d_in[8];
    float* out = (float*)d_out;

    float *pQ, *pQd, *pK, *pKd, *pV, *pAtt;
    cudaGetSymbolAddress((void**)&pQ,  g_Q);
    cudaGetSymbolAddress((void**)&pQd, g_Qd);
    cudaGetSymbolAddress((void**)&pK,  g_K);
    cudaGetSymbolAddress((void**)&pKd, g_Kd);
    cudaGetSymbolAddress((void**)&pV,  g_V);
    cudaGetSymbolAddress((void**)&pAtt, g_att);

    const int FLASH_SMEM = (4 * 64 * 68 + 64) * 4;   // 69888 B
    static int configured = 0;
    if (!configured) {
        cudaFuncSetAttribute(flash_kernel, cudaFuncAttributeMaxDynamicSharedMemorySize, FLASH_SMEM);
        configured = 1;
    }

    dim3 blk(256);

    // score-path projections (3-term): Wq, Wk   -- fused, z in {0,1}
    mma_gemm<0,3><<<dim3(8, 32, 2), blk>>>(qi, Wq, pQ,
                                           ki, Wk, pK,
                                           qi, Wq, pQ);
    // tolerant projections (2-term): Wqd, Wkd, Wv -- fused, z in {0,1,2}
    mma_gemm<0,2><<<dim3(8, 32, 3), blk>>>(qi, Wqd, pQd,
                                           ki, Wkd, pKd,
                                           vi, Wv,  pV);

    defw_kernel <<<dim3(32, 32), dim3(128)>>>();
    flash_kernel<<<dim3(32, 32), dim3(128), FLASH_SMEM>>>();

    // output projection (2-term)
    mma_gemm<1,2><<<dim3(8, 32, 1), blk>>>(pAtt, Wo, out,
                                           pAtt, Wo, out,
                                           pAtt, Wo, out);
}